// round 1
// baseline (speedup 1.0000x reference)
#include <cuda_runtime.h>
#include <math.h>

// Problem constants
#define BB 8
#define TT 448
#define SS 1500
#define DD 1024
#define HH 16
#define DH 64

#define OUT_ELEMS (BB*TT*DD)          // 3,670,016

// Scratch (static device allocations are the sanctioned scratch mechanism)
__device__ float g_q [BB*TT*DD];
__device__ float g_k [BB*SS*DD];
__device__ float g_v [BB*SS*DD];
__device__ float g_wv[BB*TT*DD];

// ---------------------------------------------------------------------------
// SGEMM: C[M,N] = (A[M,K] @ B[K,N] + bias[N]) * alpha     (bias may be null)
// 128x128 tile, BK=16, 256 threads, 8x8 per-thread microtile.
// N and K must be multiples of 128/16 (true here: N=K=1024). M is guarded.
// ---------------------------------------------------------------------------
__global__ __launch_bounds__(256) void sgemm_kernel(
    const float* __restrict__ A, const float* __restrict__ Bm,
    const float* __restrict__ bias, float* __restrict__ C,
    int M, int N, int K, float alpha)
{
    __shared__ float As[16 * 132];   // transposed: As[k][m], padded stride 132
    __shared__ float Bs[16 * 128];   // Bs[k][n]

    const int tid = threadIdx.x;
    const int m0  = blockIdx.y * 128;
    const int n0  = blockIdx.x * 128;
    const int ty4 = (tid >> 4) * 4;  // 0..60
    const int tx4 = (tid & 15) * 4;  // 0..60

    float acc[8][8];
#pragma unroll
    for (int i = 0; i < 8; i++)
#pragma unroll
        for (int j = 0; j < 8; j++) acc[i][j] = 0.f;

    for (int k0 = 0; k0 < K; k0 += 16) {
#pragma unroll
        for (int jj = 0; jj < 2; jj++) {
            int idx = tid + jj * 256;            // 0..511
            // --- A tile: 128 rows x 16 cols, store transposed ---
            int ar = idx >> 2;                   // 0..127
            int ac = (idx & 3) << 2;             // 0,4,8,12
            float4 av = make_float4(0.f, 0.f, 0.f, 0.f);
            if (m0 + ar < M)
                av = *(const float4*)(A + (size_t)(m0 + ar) * K + k0 + ac);
            As[(ac + 0) * 132 + ar] = av.x;
            As[(ac + 1) * 132 + ar] = av.y;
            As[(ac + 2) * 132 + ar] = av.z;
            As[(ac + 3) * 132 + ar] = av.w;
            // --- B tile: 16 rows x 128 cols ---
            int br = idx >> 5;                   // 0..15
            int bc = (idx & 31) << 2;            // 0..124
            float4 bv = *(const float4*)(Bm + (size_t)(k0 + br) * N + n0 + bc);
            *(float4*)(Bs + br * 128 + bc) = bv;
        }
        __syncthreads();

#pragma unroll
        for (int kk = 0; kk < 16; kk++) {
            float a[8], b[8];
            *(float4*)&a[0] = *(const float4*)(As + kk * 132 + ty4);
            *(float4*)&a[4] = *(const float4*)(As + kk * 132 + ty4 + 64);
            *(float4*)&b[0] = *(const float4*)(Bs + kk * 128 + tx4);
            *(float4*)&b[4] = *(const float4*)(Bs + kk * 128 + tx4 + 64);
#pragma unroll
            for (int i = 0; i < 8; i++)
#pragma unroll
                for (int j = 0; j < 8; j++)
                    acc[i][j] += a[i] * b[j];
        }
        __syncthreads();
    }

    // Epilogue: (acc + bias) * alpha
    float bf[8];
#pragma unroll
    for (int j = 0; j < 8; j++) bf[j] = 0.f;
    if (bias) {
        *(float4*)&bf[0] = *(const float4*)(bias + n0 + tx4);
        *(float4*)&bf[4] = *(const float4*)(bias + n0 + tx4 + 64);
    }
#pragma unroll
    for (int ih = 0; ih < 2; ih++) {
#pragma unroll
        for (int i = 0; i < 4; i++) {
            int row = m0 + ty4 + i + ih * 64;
            if (row < M) {
#pragma unroll
                for (int jh = 0; jh < 2; jh++) {
                    float4 r;
                    r.x = (acc[ih*4 + i][jh*4 + 0] + bf[jh*4 + 0]) * alpha;
                    r.y = (acc[ih*4 + i][jh*4 + 1] + bf[jh*4 + 1]) * alpha;
                    r.z = (acc[ih*4 + i][jh*4 + 2] + bf[jh*4 + 2]) * alpha;
                    r.w = (acc[ih*4 + i][jh*4 + 3] + bf[jh*4 + 3]) * alpha;
                    *(float4*)(C + (size_t)row * N + n0 + tx4 + jh * 64) = r;
                }
            }
        }
    }
}

// ---------------------------------------------------------------------------
// Flash-style attention per (b, h, 64-row q-tile).
// Streams S in chunks of 64: computes logits (scale already folded into q,k),
// writes raw logits to qk_out, online softmax, accumulates PV in registers,
// writes normalized result to wv_out.
// grid (7, 128) block 256, dynamic smem 70144 B.
// ---------------------------------------------------------------------------
__global__ __launch_bounds__(256) void attn_kernel(
    const float* __restrict__ q, const float* __restrict__ k,
    const float* __restrict__ v, float* __restrict__ qk_out,
    float* __restrict__ wv_out)
{
    extern __shared__ float sm[];
    float* Qs   = sm;               // [64][68]
    float* Ks   = Qs + 64 * 68;     // [64][68]
    float* Vs   = Ks + 64 * 68;     // [64][68]
    float* Ps   = Vs + 64 * 68;     // [64][68]
    float* corr = Ps + 64 * 68;     // [64]
    float* linv = corr + 64;        // [64]

    const int tid = threadIdx.x;
    const int bh  = blockIdx.y;
    const int b   = bh >> 4;
    const int h   = bh & 15;
    const int t0  = blockIdx.x * 64;
    const int ty4 = (tid >> 4) * 4;   // q-row group
    const int tx4 = (tid & 15) * 4;   // s-col / d-col group

    // Load Q tile [64 rows x 64 dims]
#pragma unroll
    for (int jj = 0; jj < 4; jj++) {
        int idx = tid + jj * 256;        // 0..1023 float4s
        int row = idx >> 4;              // 0..63
        int col = (idx & 15) << 2;       // 0..60
        float4 val = *(const float4*)(q + (size_t)(b * TT + t0 + row) * DD + h * DH + col);
        *(float4*)(Qs + row * 68 + col) = val;
    }

    float m_i = -INFINITY, l_i = 0.f;   // valid in threads 0..63 (row = tid)
    float o[4][4];
#pragma unroll
    for (int i = 0; i < 4; i++)
#pragma unroll
        for (int j = 0; j < 4; j++) o[i][j] = 0.f;

    __syncthreads();

    for (int s0 = 0; s0 < SS; s0 += 64) {
        const int sc = min(64, SS - s0);

        // Load K,V chunk [64 x 64], zero-fill past S
#pragma unroll
        for (int jj = 0; jj < 4; jj++) {
            int idx = tid + jj * 256;
            int row = idx >> 4;
            int col = (idx & 15) << 2;
            float4 kv = make_float4(0.f, 0.f, 0.f, 0.f);
            float4 vv = kv;
            if (s0 + row < SS) {
                size_t base = (size_t)(b * SS + s0 + row) * DD + h * DH + col;
                kv = *(const float4*)(k + base);
                vv = *(const float4*)(v + base);
            }
            *(float4*)(Ks + row * 68 + col) = kv;
            *(float4*)(Vs + row * 68 + col) = vv;
        }
        __syncthreads();

        // Logits: acc[i][j] = sum_d Qs[ty4+i][d] * Ks[tx4+j][d]
        float acc[4][4];
#pragma unroll
        for (int i = 0; i < 4; i++)
#pragma unroll
            for (int j = 0; j < 4; j++) acc[i][j] = 0.f;

#pragma unroll
        for (int d = 0; d < 64; d += 4) {
            float4 qv[4], kv[4];
#pragma unroll
            for (int i = 0; i < 4; i++)
                qv[i] = *(const float4*)(Qs + (ty4 + i) * 68 + d);
#pragma unroll
            for (int j = 0; j < 4; j++)
                kv[j] = *(const float4*)(Ks + (tx4 + j) * 68 + d);
#pragma unroll
            for (int i = 0; i < 4; i++)
#pragma unroll
                for (int j = 0; j < 4; j++)
                    acc[i][j] += qv[i].x * kv[j].x + qv[i].y * kv[j].y
                               + qv[i].z * kv[j].z + qv[i].w * kv[j].w;
        }

        // Write raw logits to qk output + stash in Ps for softmax
#pragma unroll
        for (int i = 0; i < 4; i++) {
            int t = t0 + ty4 + i;
            float* dst = qk_out + ((size_t)(bh * TT + t)) * SS + s0 + tx4;
            if (tx4 + 4 <= sc) {
                *(float4*)dst = make_float4(acc[i][0], acc[i][1], acc[i][2], acc[i][3]);
            } else {
#pragma unroll
                for (int j = 0; j < 4; j++)
                    if (tx4 + j < sc) dst[j] = acc[i][j];
            }
            *(float4*)(Ps + (ty4 + i) * 68 + tx4) =
                make_float4(acc[i][0], acc[i][1], acc[i][2], acc[i][3]);
        }
        __syncthreads();

        // Online softmax per row (threads 0..63, row = tid)
        if (tid < 64) {
            float* prow = Ps + tid * 68;
            float mloc = -INFINITY;
            for (int s = 0; s < sc; s++) mloc = fmaxf(mloc, prow[s]);
            float m_new = fmaxf(m_i, mloc);
            float c = __expf(m_i - m_new);
            float sum = 0.f;
            for (int s = 0; s < sc; s++) {
                float p = __expf(prow[s] - m_new);
                prow[s] = p;
                sum += p;
            }
            for (int s = sc; s < 64; s++) prow[s] = 0.f;
            l_i = l_i * c + sum;
            m_i = m_new;
            corr[tid] = c;
        }
        __syncthreads();

        // Rescale o and accumulate PV: o[i][dj] += sum_s Ps[r][s] * Vs[s][d]
        float cr[4];
#pragma unroll
        for (int i = 0; i < 4; i++) cr[i] = corr[ty4 + i];
#pragma unroll
        for (int i = 0; i < 4; i++)
#pragma unroll
            for (int j = 0; j < 4; j++) o[i][j] *= cr[i];

#pragma unroll
        for (int s = 0; s < 64; s += 4) {
            float4 pv[4], vv[4];
#pragma unroll
            for (int i = 0; i < 4; i++)
                pv[i] = *(const float4*)(Ps + (ty4 + i) * 68 + s);
#pragma unroll
            for (int j = 0; j < 4; j++)
                vv[j] = *(const float4*)(Vs + (s + j) * 68 + tx4);
#pragma unroll
            for (int i = 0; i < 4; i++) {
                o[i][0] += pv[i].x * vv[0].x + pv[i].y * vv[1].x + pv[i].z * vv[2].x + pv[i].w * vv[3].x;
                o[i][1] += pv[i].x * vv[0].y + pv[i].y * vv[1].y + pv[i].z * vv[2].y + pv[i].w * vv[3].y;
                o[i][2] += pv[i].x * vv[0].z + pv[i].y * vv[1].z + pv[i].z * vv[2].z + pv[i].w * vv[3].z;
                o[i][3] += pv[i].x * vv[0].w + pv[i].y * vv[1].w + pv[i].z * vv[2].w + pv[i].w * vv[3].w;
            }
        }
        __syncthreads();   // protect Ks/Vs/Ps before next chunk load
    }

    // Normalize and write wv
    if (tid < 64) linv[tid] = 1.f / l_i;
    __syncthreads();
#pragma unroll
    for (int i = 0; i < 4; i++) {
        int t = t0 + ty4 + i;
        float s = linv[ty4 + i];
        float4 r = make_float4(o[i][0] * s, o[i][1] * s, o[i][2] * s, o[i][3] * s);
        *(float4*)(wv_out + (size_t)(b * TT + t) * DD + h * DH + tx4) = r;
    }
}

// ---------------------------------------------------------------------------
extern "C" void kernel_launch(void* const* d_in, const int* in_sizes, int n_in,
                              void* d_out, int out_size)
{
    const float* x  = (const float*)d_in[0];
    const float* xa = (const float*)d_in[1];
    const float* Wq = (const float*)d_in[2];
    const float* bq = (const float*)d_in[3];
    const float* Wk = (const float*)d_in[4];
    const float* Wv = (const float*)d_in[5];
    const float* bv = (const float*)d_in[6];
    const float* Wo = (const float*)d_in[7];
    const float* bo = (const float*)d_in[8];

    float* out = (float*)d_out;               // [8,448,1024]
    float* qk  = out + OUT_ELEMS;             // [8,16,448,1500]

    float* q_s  = nullptr; cudaGetSymbolAddress((void**)&q_s,  g_q);
    float* k_s  = nullptr; cudaGetSymbolAddress((void**)&k_s,  g_k);
    float* v_s  = nullptr; cudaGetSymbolAddress((void**)&v_s,  g_v);
    float* wv_s = nullptr; cudaGetSymbolAddress((void**)&wv_s, g_wv);

    const float scale = 0.3535533905932738f;  // 64^-0.25

    dim3 blk(256);
    // q = (x @ Wq + bq) * scale   [3584,1024]
    sgemm_kernel<<<dim3(DD/128, (BB*TT + 127)/128), blk>>>(x, Wq, bq, q_s, BB*TT, DD, DD, scale);
    // k = (xa @ Wk) * scale       [12000,1024]
    sgemm_kernel<<<dim3(DD/128, (BB*SS + 127)/128), blk>>>(xa, Wk, nullptr, k_s, BB*SS, DD, DD, scale);
    // v = xa @ Wv + bv            [12000,1024]
    sgemm_kernel<<<dim3(DD/128, (BB*SS + 127)/128), blk>>>(xa, Wv, bv, v_s, BB*SS, DD, DD, 1.0f);

    // attention: logits -> qk, softmax+PV -> wv
    static const size_t attn_smem = (4 * 64 * 68 + 128) * sizeof(float);  // 70144 B
    cudaFuncSetAttribute(attn_kernel, cudaFuncAttributeMaxDynamicSharedMemorySize, (int)attn_smem);
    attn_kernel<<<dim3(TT/64, BB*HH), blk, attn_smem>>>(q_s, k_s, v_s, qk, wv_s);

    // out = wv @ Wo + bo          [3584,1024]
    sgemm_kernel<<<dim3(DD/128, (BB*TT + 127)/128), blk>>>(wv_s, Wo, bo, out, BB*TT, DD, DD, 1.0f);
}

// round 2
// speedup vs baseline: 1.9729x; 1.9729x over previous
#include <cuda_runtime.h>
#include <math.h>
#include <stdint.h>

// Problem constants
#define BB 8
#define TT 448
#define SS 1500
#define DD 1024
#define HH 16
#define DH 64
#define OUT_ELEMS (BB*TT*DD)

// Scratch
__device__ float g_q [BB*TT*DD];
__device__ float g_k [BB*SS*DD];
__device__ float g_v [BB*SS*DD];
__device__ float g_wv[BB*TT*DD];

// ---------------------------------------------------------------------------
// tf32 helpers
// ---------------------------------------------------------------------------
__device__ __forceinline__ uint32_t f2tf32(float f) {
    uint32_t r;
    asm("cvt.rna.tf32.f32 %0, %1;" : "=r"(r) : "f"(f));
    return r;
}
__device__ __forceinline__ float4 cvt4(float4 v) {
    return make_float4(__uint_as_float(f2tf32(v.x)), __uint_as_float(f2tf32(v.y)),
                       __uint_as_float(f2tf32(v.z)), __uint_as_float(f2tf32(v.w)));
}
// D(16x8,f32) += A(16x8,tf32,row) * B(8x8,tf32,col)
__device__ __forceinline__ void mma8(float* c, const uint32_t* a, const uint32_t* b) {
    asm volatile("mma.sync.aligned.m16n8k8.row.col.f32.tf32.tf32.f32 "
        "{%0,%1,%2,%3}, {%4,%5,%6,%7}, {%8,%9}, {%0,%1,%2,%3};"
        : "+f"(c[0]), "+f"(c[1]), "+f"(c[2]), "+f"(c[3])
        : "r"(a[0]), "r"(a[1]), "r"(a[2]), "r"(a[3]), "r"(b[0]), "r"(b[1]));
}

// ---------------------------------------------------------------------------
// tf32 GEMM: C[M,N] = (A[M,K] @ B[K,N] + bias) * alpha
// 128x128 block tile, BK=32, 256 threads (8 warps, 2x4), warp tile 64x32.
// ---------------------------------------------------------------------------
#define ASTR 36
#define BSTR 136

__global__ __launch_bounds__(256) void gemm_tf32(
    const float* __restrict__ A, const float* __restrict__ Bm,
    const float* __restrict__ bias, float* __restrict__ C,
    int M, int N, int K, float alpha)
{
    __shared__ float As[128 * ASTR];   // [m][k] padded
    __shared__ float Bs[32  * BSTR];   // [k][n] padded

    const int tid  = threadIdx.x;
    const int warp = tid >> 5, lane = tid & 31;
    const int wm = warp >> 2, wn = warp & 3;   // warp grid 2 x 4
    const int g  = lane >> 2, tg = lane & 3;   // groupID, tid-in-group
    const int m0 = blockIdx.y * 128, n0 = blockIdx.x * 128;

    float acc[4][4][4];
#pragma unroll
    for (int mi = 0; mi < 4; mi++)
#pragma unroll
        for (int nj = 0; nj < 4; nj++)
#pragma unroll
            for (int r = 0; r < 4; r++) acc[mi][nj][r] = 0.f;

    for (int k0 = 0; k0 < K; k0 += 32) {
        // Load A(128x32) and B(32x128): 4 float4 each per thread, cvt to tf32.
#pragma unroll
        for (int i = 0; i < 4; i++) {
            int idx = tid + i * 256;
            int ra = idx >> 3, ca = (idx & 7) << 2;
            float4 av = make_float4(0.f, 0.f, 0.f, 0.f);
            if (m0 + ra < M)
                av = *(const float4*)(A + (size_t)(m0 + ra) * K + k0 + ca);
            *(float4*)(As + ra * ASTR + ca) = cvt4(av);

            int rb = idx >> 5, cb = (idx & 31) << 2;
            float4 bvv = *(const float4*)(Bm + (size_t)(k0 + rb) * N + n0 + cb);
            *(float4*)(Bs + rb * BSTR + cb) = cvt4(bvv);
        }
        __syncthreads();

#pragma unroll
        for (int kk = 0; kk < 32; kk += 8) {
            uint32_t af[4][4], bf[4][2];
#pragma unroll
            for (int mi = 0; mi < 4; mi++) {
                int row = wm * 64 + mi * 16 + g;
                af[mi][0] = __float_as_uint(As[row * ASTR + kk + tg]);
                af[mi][1] = __float_as_uint(As[(row + 8) * ASTR + kk + tg]);
                af[mi][2] = __float_as_uint(As[row * ASTR + kk + tg + 4]);
                af[mi][3] = __float_as_uint(As[(row + 8) * ASTR + kk + tg + 4]);
            }
#pragma unroll
            for (int nj = 0; nj < 4; nj++) {
                int col = wn * 32 + nj * 8 + g;
                bf[nj][0] = __float_as_uint(Bs[(kk + tg) * BSTR + col]);
                bf[nj][1] = __float_as_uint(Bs[(kk + tg + 4) * BSTR + col]);
            }
#pragma unroll
            for (int mi = 0; mi < 4; mi++)
#pragma unroll
                for (int nj = 0; nj < 4; nj++)
                    mma8(acc[mi][nj], af[mi], bf[nj]);
        }
        __syncthreads();
    }

    // Epilogue
#pragma unroll
    for (int nj = 0; nj < 4; nj++) {
        int col = n0 + wn * 32 + nj * 8 + tg * 2;
        float2 bv = make_float2(0.f, 0.f);
        if (bias) bv = *(const float2*)(bias + col);
#pragma unroll
        for (int mi = 0; mi < 4; mi++) {
            int r0 = m0 + wm * 64 + mi * 16 + g;
            if (r0 < M) {
                float2 o = make_float2((acc[mi][nj][0] + bv.x) * alpha,
                                       (acc[mi][nj][1] + bv.y) * alpha);
                *(float2*)(C + (size_t)r0 * N + col) = o;
            }
            if (r0 + 8 < M) {
                float2 o = make_float2((acc[mi][nj][2] + bv.x) * alpha,
                                       (acc[mi][nj][3] + bv.y) * alpha);
                *(float2*)(C + (size_t)(r0 + 8) * N + col) = o;
            }
        }
    }
}

// ---------------------------------------------------------------------------
// tf32 flash attention per (b, h, 64-row q-tile). 4 warps (2x2), 128 threads.
// Streams S in 64-chunks: QK^T via mma -> raw logits to qk_out -> online
// softmax (quad shuffles + smem combine) -> PV via mma.
// ---------------------------------------------------------------------------
#define PSTR 72

__global__ __launch_bounds__(128) void attn_tf32(
    const float* __restrict__ q, const float* __restrict__ k,
    const float* __restrict__ v, float* __restrict__ qk_out,
    float* __restrict__ wv_out)
{
    extern __shared__ float sm[];
    float* Qs     = sm;                 // [64][72] tf32
    float* Ks     = Qs + 64 * PSTR;     // [64][72] tf32
    float* Vs     = Ks + 64 * PSTR;     // [64][72] tf32
    float* Ps     = Vs + 64 * PSTR;     // [64][72] tf32 (exp'd probs)
    float* m_s    = Ps + 64 * PSTR;     // [64]
    float* l_s    = m_s + 64;           // [64]
    float* corr_s = l_s + 64;           // [64]
    float* pmax   = corr_s + 64;        // [128]  (row, wn)
    float* psum   = pmax + 128;         // [128]

    const int tid  = threadIdx.x;
    const int warp = tid >> 5, lane = tid & 31;
    const int wm = warp >> 1, wn = warp & 1;   // 2 x 2 warp grid
    const int g  = lane >> 2, tg = lane & 3;
    const int bh = blockIdx.y;
    const int b  = bh >> 4, h = bh & 15;
    const int t0 = blockIdx.x * 64;

    // Load Q tile [64][64] -> tf32 smem
#pragma unroll
    for (int i = 0; i < 8; i++) {
        int idx = tid + i * 128;
        int r = idx >> 4, c = (idx & 15) << 2;
        float4 val = *(const float4*)(q + (size_t)(b * TT + t0 + r) * DD + h * DH + c);
        *(float4*)(Qs + r * PSTR + c) = cvt4(val);
    }
    if (tid < 64) { m_s[tid] = -INFINITY; l_s[tid] = 0.f; }

    float o[2][4][4];
#pragma unroll
    for (int mi = 0; mi < 2; mi++)
#pragma unroll
        for (int nj = 0; nj < 4; nj++)
#pragma unroll
            for (int r = 0; r < 4; r++) o[mi][nj][r] = 0.f;

    __syncthreads();

    for (int s0 = 0; s0 < SS; s0 += 64) {
        const int sc = min(64, SS - s0);

        // Load K,V chunk [64][64] (zero-fill past S) -> tf32 smem
#pragma unroll
        for (int i = 0; i < 8; i++) {
            int idx = tid + i * 128;
            int r = idx >> 4, c = (idx & 15) << 2;
            float4 kv = make_float4(0.f, 0.f, 0.f, 0.f);
            float4 vv = make_float4(0.f, 0.f, 0.f, 0.f);
            if (s0 + r < SS) {
                size_t base = (size_t)(b * SS + s0 + r) * DD + h * DH + c;
                kv = *(const float4*)(k + base);
                vv = *(const float4*)(v + base);
            }
            *(float4*)(Ks + r * PSTR + c) = cvt4(kv);
            *(float4*)(Vs + r * PSTR + c) = cvt4(vv);
        }
        __syncthreads();

        // --- QK^T: logits frags [mi][nj][4], 64x64 over 2x2 warps ---
        float qa[2][4][4];
#pragma unroll
        for (int mi = 0; mi < 2; mi++)
#pragma unroll
            for (int nj = 0; nj < 4; nj++)
#pragma unroll
                for (int r = 0; r < 4; r++) qa[mi][nj][r] = 0.f;

#pragma unroll
        for (int kk = 0; kk < 64; kk += 8) {
            uint32_t af[2][4], bf[4][2];
#pragma unroll
            for (int mi = 0; mi < 2; mi++) {
                int row = wm * 32 + mi * 16 + g;
                af[mi][0] = __float_as_uint(Qs[row * PSTR + kk + tg]);
                af[mi][1] = __float_as_uint(Qs[(row + 8) * PSTR + kk + tg]);
                af[mi][2] = __float_as_uint(Qs[row * PSTR + kk + tg + 4]);
                af[mi][3] = __float_as_uint(Qs[(row + 8) * PSTR + kk + tg + 4]);
            }
#pragma unroll
            for (int nj = 0; nj < 4; nj++) {
                int scol = wn * 32 + nj * 8 + g;
                bf[nj][0] = __float_as_uint(Ks[scol * PSTR + kk + tg]);      // B[k=d][n=s]=K[s][d]
                bf[nj][1] = __float_as_uint(Ks[scol * PSTR + kk + tg + 4]);
            }
#pragma unroll
            for (int mi = 0; mi < 2; mi++)
#pragma unroll
                for (int nj = 0; nj < 4; nj++)
                    mma8(qa[mi][nj], af[mi], bf[nj]);
        }

        // --- write raw logits to qk_out; mask out-of-range cols ---
#pragma unroll
        for (int mi = 0; mi < 2; mi++) {
            int r0 = wm * 32 + mi * 16 + g;
#pragma unroll
            for (int nj = 0; nj < 4; nj++) {
                int col = wn * 32 + nj * 8 + tg * 2;
                if (col < sc) {  // col even, sc even -> col+1 < sc too
                    *(float2*)(qk_out + ((size_t)bh * TT + t0 + r0) * SS + s0 + col)
                        = make_float2(qa[mi][nj][0], qa[mi][nj][1]);
                    *(float2*)(qk_out + ((size_t)bh * TT + t0 + r0 + 8) * SS + s0 + col)
                        = make_float2(qa[mi][nj][2], qa[mi][nj][3]);
                } else {
                    qa[mi][nj][0] = qa[mi][nj][1] = -1e30f;
                    qa[mi][nj][2] = qa[mi][nj][3] = -1e30f;
                }
            }
        }

        // --- row max: per-thread over 8 vals/row, quad shuffle reduce ---
        float rmax[2][2];
#pragma unroll
        for (int mi = 0; mi < 2; mi++) {
            float m0v = -INFINITY, m1v = -INFINITY;
#pragma unroll
            for (int nj = 0; nj < 4; nj++) {
                m0v = fmaxf(m0v, fmaxf(qa[mi][nj][0], qa[mi][nj][1]));
                m1v = fmaxf(m1v, fmaxf(qa[mi][nj][2], qa[mi][nj][3]));
            }
            rmax[mi][0] = m0v; rmax[mi][1] = m1v;
        }
#pragma unroll
        for (int mi = 0; mi < 2; mi++)
#pragma unroll
            for (int h2 = 0; h2 < 2; h2++) {
                float vmx = rmax[mi][h2];
                vmx = fmaxf(vmx, __shfl_xor_sync(0xffffffffu, vmx, 1));
                vmx = fmaxf(vmx, __shfl_xor_sync(0xffffffffu, vmx, 2));
                rmax[mi][h2] = vmx;
            }
        if (tg == 0) {
#pragma unroll
            for (int mi = 0; mi < 2; mi++)
#pragma unroll
                for (int h2 = 0; h2 < 2; h2++)
                    pmax[(wm * 32 + mi * 16 + h2 * 8 + g) * 2 + wn] = rmax[mi][h2];
        }
        __syncthreads();

        if (tid < 64) {
            float mo = m_s[tid];
            float mn = fmaxf(mo, fmaxf(pmax[2 * tid], pmax[2 * tid + 1]));
            corr_s[tid] = __expf(mo - mn);
            m_s[tid] = mn;
        }
        __syncthreads();

        // --- exp, store P to smem (tf32), partial row sums ---
        float rsum[2][2] = {{0.f, 0.f}, {0.f, 0.f}};
#pragma unroll
        for (int mi = 0; mi < 2; mi++) {
#pragma unroll
            for (int h2 = 0; h2 < 2; h2++) {
                int row = wm * 32 + mi * 16 + h2 * 8 + g;
                float mn = m_s[row];
#pragma unroll
                for (int nj = 0; nj < 4; nj++) {
                    int ri = h2 * 2;
                    float p0 = __expf(qa[mi][nj][ri]     - mn);
                    float p1 = __expf(qa[mi][nj][ri + 1] - mn);
                    rsum[mi][h2] += p0 + p1;
                    int col = wn * 32 + nj * 8 + tg * 2;
                    *(float2*)(Ps + row * PSTR + col) =
                        make_float2(__uint_as_float(f2tf32(p0)),
                                    __uint_as_float(f2tf32(p1)));
                }
            }
        }
#pragma unroll
        for (int mi = 0; mi < 2; mi++)
#pragma unroll
            for (int h2 = 0; h2 < 2; h2++) {
                float s = rsum[mi][h2];
                s += __shfl_xor_sync(0xffffffffu, s, 1);
                s += __shfl_xor_sync(0xffffffffu, s, 2);
                rsum[mi][h2] = s;
            }
        if (tg == 0) {
#pragma unroll
            for (int mi = 0; mi < 2; mi++)
#pragma unroll
                for (int h2 = 0; h2 < 2; h2++)
                    psum[(wm * 32 + mi * 16 + h2 * 8 + g) * 2 + wn] = rsum[mi][h2];
        }
        __syncthreads();   // Ps fully written + psum ready

        if (tid < 64)
            l_s[tid] = l_s[tid] * corr_s[tid] + psum[2 * tid] + psum[2 * tid + 1];

        // --- rescale O by correction factor ---
#pragma unroll
        for (int mi = 0; mi < 2; mi++)
#pragma unroll
            for (int h2 = 0; h2 < 2; h2++) {
                float c = corr_s[wm * 32 + mi * 16 + h2 * 8 + g];
#pragma unroll
                for (int nj = 0; nj < 4; nj++) {
                    o[mi][nj][h2 * 2]     *= c;
                    o[mi][nj][h2 * 2 + 1] *= c;
                }
            }

        // --- PV: O += P @ V ---
#pragma unroll
        for (int kk = 0; kk < 64; kk += 8) {
            uint32_t af[2][4], bf[4][2];
#pragma unroll
            for (int mi = 0; mi < 2; mi++) {
                int row = wm * 32 + mi * 16 + g;
                af[mi][0] = __float_as_uint(Ps[row * PSTR + kk + tg]);
                af[mi][1] = __float_as_uint(Ps[(row + 8) * PSTR + kk + tg]);
                af[mi][2] = __float_as_uint(Ps[row * PSTR + kk + tg + 4]);
                af[mi][3] = __float_as_uint(Ps[(row + 8) * PSTR + kk + tg + 4]);
            }
#pragma unroll
            for (int nj = 0; nj < 4; nj++) {
                int dcol = wn * 32 + nj * 8 + g;
                bf[nj][0] = __float_as_uint(Vs[(kk + tg) * PSTR + dcol]);    // B[k=s][n=d]=V[s][d]
                bf[nj][1] = __float_as_uint(Vs[(kk + tg + 4) * PSTR + dcol]);
            }
#pragma unroll
            for (int mi = 0; mi < 2; mi++)
#pragma unroll
                for (int nj = 0; nj < 4; nj++)
                    mma8(o[mi][nj], af[mi], bf[nj]);
        }
        __syncthreads();   // protect Ks/Vs/Ps/pmax before next chunk
    }

    if (tid < 64) l_s[tid] = 1.f / l_s[tid];
    __syncthreads();

#pragma unroll
    for (int mi = 0; mi < 2; mi++)
#pragma unroll
        for (int h2 = 0; h2 < 2; h2++) {
            int row = wm * 32 + mi * 16 + h2 * 8 + g;
            float inv = l_s[row];
#pragma unroll
            for (int nj = 0; nj < 4; nj++) {
                int col = wn * 32 + nj * 8 + tg * 2;
                float2 r = make_float2(o[mi][nj][h2 * 2] * inv,
                                       o[mi][nj][h2 * 2 + 1] * inv);
                *(float2*)(wv_out + (size_t)(b * TT + t0 + row) * DD + h * DH + col) = r;
            }
        }
}

// ---------------------------------------------------------------------------
extern "C" void kernel_launch(void* const* d_in, const int* in_sizes, int n_in,
                              void* d_out, int out_size)
{
    const float* x  = (const float*)d_in[0];
    const float* xa = (const float*)d_in[1];
    const float* Wq = (const float*)d_in[2];
    const float* bq = (const float*)d_in[3];
    const float* Wk = (const float*)d_in[4];
    const float* Wv = (const float*)d_in[5];
    const float* bv = (const float*)d_in[6];
    const float* Wo = (const float*)d_in[7];
    const float* bo = (const float*)d_in[8];

    float* out = (float*)d_out;               // [8,448,1024]
    float* qk  = out + OUT_ELEMS;             // [8,16,448,1500]

    float* q_s  = nullptr; cudaGetSymbolAddress((void**)&q_s,  g_q);
    float* k_s  = nullptr; cudaGetSymbolAddress((void**)&k_s,  g_k);
    float* v_s  = nullptr; cudaGetSymbolAddress((void**)&v_s,  g_v);
    float* wv_s = nullptr; cudaGetSymbolAddress((void**)&wv_s, g_wv);

    const float scale = 0.3535533905932738f;  // 64^-0.25

    dim3 blk(256);
    gemm_tf32<<<dim3(DD/128, (BB*TT + 127)/128), blk>>>(x,  Wq, bq,      q_s, BB*TT, DD, DD, scale);
    gemm_tf32<<<dim3(DD/128, (BB*SS + 127)/128), blk>>>(xa, Wk, nullptr, k_s, BB*SS, DD, DD, scale);
    gemm_tf32<<<dim3(DD/128, (BB*SS + 127)/128), blk>>>(xa, Wv, bv,      v_s, BB*SS, DD, DD, 1.0f);

    static const size_t attn_smem = (4 * 64 * PSTR + 64 * 3 + 256) * sizeof(float);  // 75520
    cudaFuncSetAttribute(attn_tf32, cudaFuncAttributeMaxDynamicSharedMemorySize, (int)attn_smem);
    attn_tf32<<<dim3(TT/64, BB*HH), dim3(128), attn_smem>>>(q_s, k_s, v_s, qk, wv_s);

    gemm_tf32<<<dim3(DD/128, (BB*TT + 127)/128), blk>>>(wv_s, Wo, bo, out, BB*TT, DD, DD, 1.0f);
}

// round 4
// speedup vs baseline: 2.7314x; 1.3845x over previous
#include <cuda_runtime.h>
#include <math.h>
#include <stdint.h>

// Problem constants
#define BB 8
#define TT 448
#define SS 1500
#define DD 1024
#define HH 16
#define DH 64
#define OUT_ELEMS (BB*TT*DD)

// Scratch
__device__ float g_q [BB*TT*DD];
__device__ float g_k [BB*SS*DD];
__device__ float g_v [BB*SS*DD];
__device__ float g_wv[BB*TT*DD];

// ---------------------------------------------------------------------------
// tf32 helpers
// ---------------------------------------------------------------------------
__device__ __forceinline__ uint32_t f2tf32(float f) {
    uint32_t r;
    asm("cvt.rna.tf32.f32 %0, %1;" : "=r"(r) : "f"(f));
    return r;
}
__device__ __forceinline__ float4 cvt4(float4 v) {
    return make_float4(__uint_as_float(f2tf32(v.x)), __uint_as_float(f2tf32(v.y)),
                       __uint_as_float(f2tf32(v.z)), __uint_as_float(f2tf32(v.w)));
}
// D(16x8,f32) += A(16x8,tf32,row) * B(8x8,tf32,col)
__device__ __forceinline__ void mma8(float* c, const uint32_t* a, const uint32_t* b) {
    asm volatile("mma.sync.aligned.m16n8k8.row.col.f32.tf32.tf32.f32 "
        "{%0,%1,%2,%3}, {%4,%5,%6,%7}, {%8,%9}, {%0,%1,%2,%3};"
        : "+f"(c[0]), "+f"(c[1]), "+f"(c[2]), "+f"(c[3])
        : "r"(a[0]), "r"(a[1]), "r"(a[2]), "r"(a[3]), "r"(b[0]), "r"(b[1]));
}

// ---------------------------------------------------------------------------
// tf32 GEMM, 2-stage double-buffered: C = (A@B + bias) * alpha
// 128x128 block tile, BK=16 ping-pong, 256 threads (8 warps 2x4), warp 64x32.
// ---------------------------------------------------------------------------
#define GASTR 20
#define GBSTR 136

__global__ __launch_bounds__(256) void gemm_tf32(
    const float* __restrict__ A, const float* __restrict__ Bm,
    const float* __restrict__ bias, float* __restrict__ C,
    int M, int N, int K, float alpha)
{
    __shared__ float As[2][128 * GASTR];   // [m][k]
    __shared__ float Bs[2][16  * GBSTR];   // [k][n]

    const int tid  = threadIdx.x;
    const int warp = tid >> 5, lane = tid & 31;
    const int wm = warp >> 2, wn = warp & 3;
    const int g  = lane >> 2, tg = lane & 3;
    const int m0 = blockIdx.y * 128, n0 = blockIdx.x * 128;

    const int ar0 = tid >> 1, ac0 = (tid & 1) << 3;   // A: rows 0..127, col 0 or 8
    const int br0 = tid >> 5, bc0 = lane << 2;        // B: rows 0..7 (+8), 128 cols

    float acc[4][4][4];
#pragma unroll
    for (int mi = 0; mi < 4; mi++)
#pragma unroll
        for (int nj = 0; nj < 4; nj++)
#pragma unroll
            for (int r = 0; r < 4; r++) acc[mi][nj][r] = 0.f;

    const int nt = K >> 4;

    // prologue: tile 0 -> stage 0
    {
        float4 a0 = make_float4(0,0,0,0), a1 = a0;
        if (m0 + ar0 < M) {
            a0 = *(const float4*)(A + (size_t)(m0 + ar0) * K + ac0);
            a1 = *(const float4*)(A + (size_t)(m0 + ar0) * K + ac0 + 4);
        }
        *(float4*)(As[0] + ar0 * GASTR + ac0)     = cvt4(a0);
        *(float4*)(As[0] + ar0 * GASTR + ac0 + 4) = cvt4(a1);
        float4 b0 = *(const float4*)(Bm + (size_t)(br0) * N + n0 + bc0);
        float4 b1 = *(const float4*)(Bm + (size_t)(br0 + 8) * N + n0 + bc0);
        *(float4*)(Bs[0] + br0 * GBSTR + bc0)       = cvt4(b0);
        *(float4*)(Bs[0] + (br0 + 8) * GBSTR + bc0) = cvt4(b1);
    }
    __syncthreads();

    for (int t = 0; t < nt; t++) {
        const int cur = t & 1;
        float4 pa0, pa1, pb0, pb1;
        const bool more = (t + 1 < nt);
        if (more) {
            const int k0 = (t + 1) << 4;
            pa0 = make_float4(0,0,0,0); pa1 = pa0;
            if (m0 + ar0 < M) {
                pa0 = *(const float4*)(A + (size_t)(m0 + ar0) * K + k0 + ac0);
                pa1 = *(const float4*)(A + (size_t)(m0 + ar0) * K + k0 + ac0 + 4);
            }
            pb0 = *(const float4*)(Bm + (size_t)(k0 + br0) * N + n0 + bc0);
            pb1 = *(const float4*)(Bm + (size_t)(k0 + br0 + 8) * N + n0 + bc0);
        }

#pragma unroll
        for (int kk = 0; kk < 16; kk += 8) {
            uint32_t af[4][4], bf[4][2];
#pragma unroll
            for (int mi = 0; mi < 4; mi++) {
                int row = wm * 64 + mi * 16 + g;
                af[mi][0] = __float_as_uint(As[cur][row * GASTR + kk + tg]);
                af[mi][1] = __float_as_uint(As[cur][(row + 8) * GASTR + kk + tg]);
                af[mi][2] = __float_as_uint(As[cur][row * GASTR + kk + tg + 4]);
                af[mi][3] = __float_as_uint(As[cur][(row + 8) * GASTR + kk + tg + 4]);
            }
#pragma unroll
            for (int nj = 0; nj < 4; nj++) {
                int col = wn * 32 + nj * 8 + g;
                bf[nj][0] = __float_as_uint(Bs[cur][(kk + tg) * GBSTR + col]);
                bf[nj][1] = __float_as_uint(Bs[cur][(kk + tg + 4) * GBSTR + col]);
            }
#pragma unroll
            for (int mi = 0; mi < 4; mi++)
#pragma unroll
                for (int nj = 0; nj < 4; nj++)
                    mma8(acc[mi][nj], af[mi], bf[nj]);
        }

        if (more) {
            const int nxt = cur ^ 1;
            *(float4*)(As[nxt] + ar0 * GASTR + ac0)       = cvt4(pa0);
            *(float4*)(As[nxt] + ar0 * GASTR + ac0 + 4)   = cvt4(pa1);
            *(float4*)(Bs[nxt] + br0 * GBSTR + bc0)       = cvt4(pb0);
            *(float4*)(Bs[nxt] + (br0 + 8) * GBSTR + bc0) = cvt4(pb1);
        }
        __syncthreads();
    }

    // Epilogue
#pragma unroll
    for (int nj = 0; nj < 4; nj++) {
        int col = n0 + wn * 32 + nj * 8 + tg * 2;
        float2 bv = make_float2(0.f, 0.f);
        if (bias) bv = *(const float2*)(bias + col);
#pragma unroll
        for (int mi = 0; mi < 4; mi++) {
            int r0 = m0 + wm * 64 + mi * 16 + g;
            if (r0 < M) {
                float2 o = make_float2((acc[mi][nj][0] + bv.x) * alpha,
                                       (acc[mi][nj][1] + bv.y) * alpha);
                *(float2*)(C + (size_t)r0 * N + col) = o;
            }
            if (r0 + 8 < M) {
                float2 o = make_float2((acc[mi][nj][2] + bv.x) * alpha,
                                       (acc[mi][nj][3] + bv.y) * alpha);
                *(float2*)(C + (size_t)(r0 + 8) * N + col) = o;
            }
        }
    }
}

// ---------------------------------------------------------------------------
// tf32 flash attention, warp-owns-full-rows layout.
// 4 warps, 128 threads; warp w owns q-rows [w*16, w*16+16), all 64 s-cols.
// ---------------------------------------------------------------------------
#define KVSTR 72
#define PQSTR 68

__global__ __launch_bounds__(128) void attn_tf32(
    const float* __restrict__ q, const float* __restrict__ k,
    const float* __restrict__ v, float* __restrict__ qk_out,
    float* __restrict__ wv_out)
{
    extern __shared__ float sm[];
    float* Ks = sm;                  // [64][72]
    float* Vs = Ks + 64 * KVSTR;     // [64][72]
    float* Ps = Vs + 64 * KVSTR;     // [64][68]  (also Q staging)

    const int tid  = threadIdx.x;
    const int warp = tid >> 5, lane = tid & 31;
    const int g  = lane >> 2, tg = lane & 3;
    const int bh = blockIdx.y;
    const int b  = bh >> 4, h = bh & 15;
    const int t0 = blockIdx.x * 64;
    const int rw = warp * 16;
    const int grow0 = t0 + rw + g;

    // ---- stage Q through smem (64x64 = 1024 float4s -> i < 8), pull frags ----
#pragma unroll
    for (int i = 0; i < 8; i++) {
        int idx = tid + i * 128;
        int r = idx >> 4, c = (idx & 15) << 2;
        float4 val = *(const float4*)(q + (size_t)(b * TT + t0 + r) * DD + h * DH + c);
        *(float4*)(Ps + r * PQSTR + c) = cvt4(val);
    }
    __syncthreads();

    uint32_t qf[8][4];
#pragma unroll
    for (int kk = 0; kk < 8; kk++) {
        int c = kk * 8;
        qf[kk][0] = __float_as_uint(Ps[(rw + g) * PQSTR + c + tg]);
        qf[kk][1] = __float_as_uint(Ps[(rw + g + 8) * PQSTR + c + tg]);
        qf[kk][2] = __float_as_uint(Ps[(rw + g) * PQSTR + c + tg + 4]);
        qf[kk][3] = __float_as_uint(Ps[(rw + g + 8) * PQSTR + c + tg + 4]);
    }

    float o[8][4];
#pragma unroll
    for (int nj = 0; nj < 8; nj++)
#pragma unroll
        for (int r = 0; r < 4; r++) o[nj][r] = 0.f;

    float m0s = -INFINITY, m1s = -INFINITY, l0s = 0.f, l1s = 0.f;

    __syncthreads();   // all Q-frag reads done before Ps reused in loop

    for (int s0 = 0; s0 < SS; s0 += 64) {
        const int sc = min(64, SS - s0);

        // ---- load K,V chunk [64][64] -> tf32 smem (zero-fill past S) ----
#pragma unroll
        for (int i = 0; i < 8; i++) {
            int idx = tid + i * 128;
            int r = idx >> 4, c = (idx & 15) << 2;
            float4 kv = make_float4(0,0,0,0), vv = kv;
            if (s0 + r < SS) {
                size_t base = (size_t)(b * SS + s0 + r) * DD + h * DH + c;
                kv = *(const float4*)(k + base);
                vv = *(const float4*)(v + base);
            }
            *(float4*)(Ks + r * KVSTR + c) = cvt4(kv);
            *(float4*)(Vs + r * KVSTR + c) = cvt4(vv);
        }
        __syncthreads();

        // ---- QK^T: 16 rows x 64 s-cols per warp ----
        float qa[8][4];
#pragma unroll
        for (int nj = 0; nj < 8; nj++)
#pragma unroll
            for (int r = 0; r < 4; r++) qa[nj][r] = 0.f;

#pragma unroll
        for (int kk = 0; kk < 8; kk++) {
            uint32_t bfr[8][2];
#pragma unroll
            for (int nj = 0; nj < 8; nj++) {
                int scol = nj * 8 + g;
                bfr[nj][0] = __float_as_uint(Ks[scol * KVSTR + kk * 8 + tg]);
                bfr[nj][1] = __float_as_uint(Ks[scol * KVSTR + kk * 8 + tg + 4]);
            }
#pragma unroll
            for (int nj = 0; nj < 8; nj++)
                mma8(qa[nj], qf[kk], bfr[nj]);
        }

        // ---- write raw logits; mask out-of-range ----
        {
            size_t rowbase = ((size_t)bh * TT + grow0) * SS + s0;
#pragma unroll
            for (int nj = 0; nj < 8; nj++) {
                int col = nj * 8 + tg * 2;
                if (col < sc) {
                    *(float2*)(qk_out + rowbase + col)          = make_float2(qa[nj][0], qa[nj][1]);
                    *(float2*)(qk_out + rowbase + 8 * SS + col) = make_float2(qa[nj][2], qa[nj][3]);
                } else {
                    qa[nj][0] = qa[nj][1] = -1e30f;
                    qa[nj][2] = qa[nj][3] = -1e30f;
                }
            }
        }

        // ---- warp-local online softmax (2 rows per thread) ----
        float mx0 = -INFINITY, mx1 = -INFINITY;
#pragma unroll
        for (int nj = 0; nj < 8; nj++) {
            mx0 = fmaxf(mx0, fmaxf(qa[nj][0], qa[nj][1]));
            mx1 = fmaxf(mx1, fmaxf(qa[nj][2], qa[nj][3]));
        }
        mx0 = fmaxf(mx0, __shfl_xor_sync(0xffffffffu, mx0, 1));
        mx0 = fmaxf(mx0, __shfl_xor_sync(0xffffffffu, mx0, 2));
        mx1 = fmaxf(mx1, __shfl_xor_sync(0xffffffffu, mx1, 1));
        mx1 = fmaxf(mx1, __shfl_xor_sync(0xffffffffu, mx1, 2));

        float mn0 = fmaxf(m0s, mx0), mn1 = fmaxf(m1s, mx1);
        float c0 = __expf(m0s - mn0), c1 = __expf(m1s - mn1);
        m0s = mn0; m1s = mn1;

        float s0r = 0.f, s1r = 0.f;
#pragma unroll
        for (int nj = 0; nj < 8; nj++) {
            float p0 = __expf(qa[nj][0] - mn0);
            float p1 = __expf(qa[nj][1] - mn0);
            float p2 = __expf(qa[nj][2] - mn1);
            float p3 = __expf(qa[nj][3] - mn1);
            s0r += p0 + p1; s1r += p2 + p3;
            qa[nj][0] = __uint_as_float(f2tf32(p0));
            qa[nj][1] = __uint_as_float(f2tf32(p1));
            qa[nj][2] = __uint_as_float(f2tf32(p2));
            qa[nj][3] = __uint_as_float(f2tf32(p3));
        }
        s0r += __shfl_xor_sync(0xffffffffu, s0r, 1);
        s0r += __shfl_xor_sync(0xffffffffu, s0r, 2);
        s1r += __shfl_xor_sync(0xffffffffu, s1r, 1);
        s1r += __shfl_xor_sync(0xffffffffu, s1r, 2);
        l0s = l0s * c0 + s0r;
        l1s = l1s * c1 + s1r;

        // rescale O
#pragma unroll
        for (int nj = 0; nj < 8; nj++) {
            o[nj][0] *= c0; o[nj][1] *= c0;
            o[nj][2] *= c1; o[nj][3] *= c1;
        }

        // ---- P -> per-warp smem slab (own rows only) ----
#pragma unroll
        for (int nj = 0; nj < 8; nj++) {
            int col = nj * 8 + tg * 2;
            *(float2*)(Ps + (rw + g) * PQSTR + col)     = make_float2(qa[nj][0], qa[nj][1]);
            *(float2*)(Ps + (rw + g + 8) * PQSTR + col) = make_float2(qa[nj][2], qa[nj][3]);
        }
        __syncwarp();

        // ---- PV: O += P @ V ----
#pragma unroll
        for (int kk = 0; kk < 8; kk++) {
            uint32_t af[4], bfr[8][2];
            af[0] = __float_as_uint(Ps[(rw + g) * PQSTR + kk * 8 + tg]);
            af[1] = __float_as_uint(Ps[(rw + g + 8) * PQSTR + kk * 8 + tg]);
            af[2] = __float_as_uint(Ps[(rw + g) * PQSTR + kk * 8 + tg + 4]);
            af[3] = __float_as_uint(Ps[(rw + g + 8) * PQSTR + kk * 8 + tg + 4]);
#pragma unroll
            for (int nj = 0; nj < 8; nj++) {
                int dcol = nj * 8 + g;
                bfr[nj][0] = __float_as_uint(Vs[(kk * 8 + tg) * KVSTR + dcol]);
                bfr[nj][1] = __float_as_uint(Vs[(kk * 8 + tg + 4) * KVSTR + dcol]);
            }
#pragma unroll
            for (int nj = 0; nj < 8; nj++)
                mma8(o[nj], af, bfr[nj]);
        }
        __syncthreads();   // protect Ks/Vs before next chunk load
    }

    // ---- normalize, write wv ----
    float inv0 = 1.f / l0s, inv1 = 1.f / l1s;
    size_t obase = (size_t)(b * TT + grow0) * DD + h * DH;
#pragma unroll
    for (int nj = 0; nj < 8; nj++) {
        int col = nj * 8 + tg * 2;
        *(float2*)(wv_out + obase + col)          = make_float2(o[nj][0] * inv0, o[nj][1] * inv0);
        *(float2*)(wv_out + obase + 8 * DD + col) = make_float2(o[nj][2] * inv1, o[nj][3] * inv1);
    }
}

// ---------------------------------------------------------------------------
extern "C" void kernel_launch(void* const* d_in, const int* in_sizes, int n_in,
                              void* d_out, int out_size)
{
    const float* x  = (const float*)d_in[0];
    const float* xa = (const float*)d_in[1];
    const float* Wq = (const float*)d_in[2];
    const float* bq = (const float*)d_in[3];
    const float* Wk = (const float*)d_in[4];
    const float* Wv = (const float*)d_in[5];
    const float* bv = (const float*)d_in[6];
    const float* Wo = (const float*)d_in[7];
    const float* bo = (const float*)d_in[8];

    float* out = (float*)d_out;               // [8,448,1024]
    float* qk  = out + OUT_ELEMS;             // [8,16,448,1500]

    float* q_s  = nullptr; cudaGetSymbolAddress((void**)&q_s,  g_q);
    float* k_s  = nullptr; cudaGetSymbolAddress((void**)&k_s,  g_k);
    float* v_s  = nullptr; cudaGetSymbolAddress((void**)&v_s,  g_v);
    float* wv_s = nullptr; cudaGetSymbolAddress((void**)&wv_s, g_wv);

    const float scale = 0.3535533905932738f;  // 64^-0.25

    dim3 blk(256);
    gemm_tf32<<<dim3(DD/128, (BB*TT + 127)/128), blk>>>(x,  Wq, bq,      q_s, BB*TT, DD, DD, scale);
    gemm_tf32<<<dim3(DD/128, (BB*SS + 127)/128), blk>>>(xa, Wk, nullptr, k_s, BB*SS, DD, DD, scale);
    gemm_tf32<<<dim3(DD/128, (BB*SS + 127)/128), blk>>>(xa, Wv, bv,      v_s, BB*SS, DD, DD, 1.0f);

    static const size_t attn_smem = (2 * 64 * KVSTR + 64 * PQSTR) * sizeof(float);  // 54272
    cudaFuncSetAttribute(attn_tf32, cudaFuncAttributeMaxDynamicSharedMemorySize, (int)attn_smem);
    attn_tf32<<<dim3(TT/64, BB*HH), dim3(128), attn_smem>>>(q_s, k_s, v_s, qk, wv_s);

    gemm_tf32<<<dim3(DD/128, (BB*TT + 127)/128), blk>>>(wv_s, Wo, bo, out, BB*TT, DD, DD, 1.0f);
}

// round 5
// speedup vs baseline: 3.4027x; 1.2458x over previous
#include <cuda_runtime.h>
#include <math.h>
#include <stdint.h>

// Problem constants
#define BB 8
#define TT 448
#define SS 1500
#define DD 1024
#define HH 16
#define DH 64
#define OUT_ELEMS (BB*TT*DD)

// Scratch
__device__ float g_q [BB*TT*DD];
__device__ float g_k [BB*SS*DD];
__device__ float g_v [BB*SS*DD];
__device__ float g_wv[BB*TT*DD];

// ---------------------------------------------------------------------------
// tf32 helpers
// ---------------------------------------------------------------------------
__device__ __forceinline__ uint32_t f2tf32(float f) {
    uint32_t r;
    asm("cvt.rna.tf32.f32 %0, %1;" : "=r"(r) : "f"(f));
    return r;
}
__device__ __forceinline__ float4 cvt4(float4 v) {
    return make_float4(__uint_as_float(f2tf32(v.x)), __uint_as_float(f2tf32(v.y)),
                       __uint_as_float(f2tf32(v.z)), __uint_as_float(f2tf32(v.w)));
}
// D(16x8,f32) += A(16x8,tf32,row) * B(8x8,tf32,col)
__device__ __forceinline__ void mma8(float* c, const uint32_t* a, const uint32_t* b) {
    asm volatile("mma.sync.aligned.m16n8k8.row.col.f32.tf32.tf32.f32 "
        "{%0,%1,%2,%3}, {%4,%5,%6,%7}, {%8,%9}, {%0,%1,%2,%3};"
        : "+f"(c[0]), "+f"(c[1]), "+f"(c[2]), "+f"(c[3])
        : "r"(a[0]), "r"(a[1]), "r"(a[2]), "r"(a[3]), "r"(b[0]), "r"(b[1]));
}

// ---------------------------------------------------------------------------
// tf32 GEMM v3: C = (A@B + bias) * alpha
// 128x128 block tile, BK=16 double-buffered, 128 threads (4 warps 2x2),
// warp tile 64x64 -> 1.0 smem-wavefront per mma (crossbar/tensor balanced).
// ---------------------------------------------------------------------------
#define GASTR 20
#define GBSTR 136

__global__ __launch_bounds__(128, 2) void gemm_tf32(
    const float* __restrict__ A, const float* __restrict__ Bm,
    const float* __restrict__ bias, float* __restrict__ C,
    int M, int N, int K, float alpha)
{
    __shared__ float As[2][128 * GASTR];   // [m][k]
    __shared__ float Bs[2][16  * GBSTR];   // [k][n]

    const int tid  = threadIdx.x;
    const int warp = tid >> 5, lane = tid & 31;
    const int wm = warp >> 1, wn = warp & 1;   // 2x2 warp grid, 64x64 tiles
    const int g  = lane >> 2, tg = lane & 3;
    const int m0 = blockIdx.y * 128, n0 = blockIdx.x * 128;

    // global load coords: 4 float4 per array per thread
    const int ar0 = tid >> 2, ac0 = (tid & 3) << 2;   // A rows ar0+32i, cols ac0
    const int br0 = tid >> 5, bc0 = lane << 2;        // B rows br0+4i, cols bc0

    float acc[4][8][4];
#pragma unroll
    for (int mi = 0; mi < 4; mi++)
#pragma unroll
        for (int nj = 0; nj < 8; nj++)
#pragma unroll
            for (int r = 0; r < 4; r++) acc[mi][nj][r] = 0.f;

    const int nt = K >> 4;

    // prologue: tile 0 -> stage 0
#pragma unroll
    for (int i = 0; i < 4; i++) {
        int ra = ar0 + i * 32;
        float4 av = make_float4(0,0,0,0);
        if (m0 + ra < M) av = *(const float4*)(A + (size_t)(m0 + ra) * K + ac0);
        *(float4*)(As[0] + ra * GASTR + ac0) = cvt4(av);
        int rb = br0 + i * 4;
        float4 bvv = *(const float4*)(Bm + (size_t)rb * N + n0 + bc0);
        *(float4*)(Bs[0] + rb * GBSTR + bc0) = cvt4(bvv);
    }
    __syncthreads();

    for (int t = 0; t < nt; t++) {
        const int cur = t & 1;
        float4 pa[4], pb[4];
        const bool more = (t + 1 < nt);
        if (more) {
            const int k0 = (t + 1) << 4;
#pragma unroll
            for (int i = 0; i < 4; i++) {
                int ra = ar0 + i * 32;
                pa[i] = make_float4(0,0,0,0);
                if (m0 + ra < M)
                    pa[i] = *(const float4*)(A + (size_t)(m0 + ra) * K + k0 + ac0);
                pb[i] = *(const float4*)(Bm + (size_t)(k0 + br0 + i * 4) * N + n0 + bc0);
            }
        }

#pragma unroll
        for (int kk = 0; kk < 16; kk += 8) {
            uint32_t af[4][4], bf[8][2];
#pragma unroll
            for (int mi = 0; mi < 4; mi++) {
                int row = wm * 64 + mi * 16 + g;
                af[mi][0] = __float_as_uint(As[cur][row * GASTR + kk + tg]);
                af[mi][1] = __float_as_uint(As[cur][(row + 8) * GASTR + kk + tg]);
                af[mi][2] = __float_as_uint(As[cur][row * GASTR + kk + tg + 4]);
                af[mi][3] = __float_as_uint(As[cur][(row + 8) * GASTR + kk + tg + 4]);
            }
#pragma unroll
            for (int nj = 0; nj < 8; nj++) {
                int col = wn * 64 + nj * 8 + g;
                bf[nj][0] = __float_as_uint(Bs[cur][(kk + tg) * GBSTR + col]);
                bf[nj][1] = __float_as_uint(Bs[cur][(kk + tg + 4) * GBSTR + col]);
            }
#pragma unroll
            for (int mi = 0; mi < 4; mi++)
#pragma unroll
                for (int nj = 0; nj < 8; nj++)
                    mma8(acc[mi][nj], af[mi], bf[nj]);
        }

        if (more) {
            const int nxt = cur ^ 1;
#pragma unroll
            for (int i = 0; i < 4; i++) {
                *(float4*)(As[nxt] + (ar0 + i * 32) * GASTR + ac0) = cvt4(pa[i]);
                *(float4*)(Bs[nxt] + (br0 + i * 4) * GBSTR + bc0)  = cvt4(pb[i]);
            }
        }
        __syncthreads();
    }

    // Epilogue
#pragma unroll
    for (int nj = 0; nj < 8; nj++) {
        int col = n0 + wn * 64 + nj * 8 + tg * 2;
        float2 bv = make_float2(0.f, 0.f);
        if (bias) bv = *(const float2*)(bias + col);
#pragma unroll
        for (int mi = 0; mi < 4; mi++) {
            int r0 = m0 + wm * 64 + mi * 16 + g;
            if (r0 < M) {
                float2 o = make_float2((acc[mi][nj][0] + bv.x) * alpha,
                                       (acc[mi][nj][1] + bv.y) * alpha);
                *(float2*)(C + (size_t)r0 * N + col) = o;
            }
            if (r0 + 8 < M) {
                float2 o = make_float2((acc[mi][nj][2] + bv.x) * alpha,
                                       (acc[mi][nj][3] + bv.y) * alpha);
                *(float2*)(C + (size_t)(r0 + 8) * N + col) = o;
            }
        }
    }
}

// ---------------------------------------------------------------------------
// tf32 flash attention, warp-owns-full-rows layout.
// 4 warps, 128 threads; warp w owns q-rows [w*16, w*16+16), all 64 s-cols.
// KSTR=68 (lanes g*4+tg distinct), VSTR=72 (lanes tg*8+g distinct):
// both fragment patterns bank-conflict-free.
// ---------------------------------------------------------------------------
#define KSTR 68
#define VSTR 72
#define PQSTR 68

__global__ __launch_bounds__(128) void attn_tf32(
    const float* __restrict__ q, const float* __restrict__ k,
    const float* __restrict__ v, float* __restrict__ qk_out,
    float* __restrict__ wv_out)
{
    extern __shared__ float sm[];
    float* Ks = sm;                  // [64][68]
    float* Vs = Ks + 64 * KSTR;      // [64][72]
    float* Ps = Vs + 64 * VSTR;      // [64][68]  (also Q staging)

    const int tid  = threadIdx.x;
    const int warp = tid >> 5, lane = tid & 31;
    const int g  = lane >> 2, tg = lane & 3;
    const int bh = blockIdx.y;
    const int b  = bh >> 4, h = bh & 15;
    const int t0 = blockIdx.x * 64;
    const int rw = warp * 16;
    const int grow0 = t0 + rw + g;

    // ---- stage Q through smem (64x64 = 1024 float4s), pull frags ----
#pragma unroll
    for (int i = 0; i < 8; i++) {
        int idx = tid + i * 128;
        int r = idx >> 4, c = (idx & 15) << 2;
        float4 val = *(const float4*)(q + (size_t)(b * TT + t0 + r) * DD + h * DH + c);
        *(float4*)(Ps + r * PQSTR + c) = cvt4(val);
    }
    __syncthreads();

    uint32_t qf[8][4];
#pragma unroll
    for (int kk = 0; kk < 8; kk++) {
        int c = kk * 8;
        qf[kk][0] = __float_as_uint(Ps[(rw + g) * PQSTR + c + tg]);
        qf[kk][1] = __float_as_uint(Ps[(rw + g + 8) * PQSTR + c + tg]);
        qf[kk][2] = __float_as_uint(Ps[(rw + g) * PQSTR + c + tg + 4]);
        qf[kk][3] = __float_as_uint(Ps[(rw + g + 8) * PQSTR + c + tg + 4]);
    }

    float o[8][4];
#pragma unroll
    for (int nj = 0; nj < 8; nj++)
#pragma unroll
        for (int r = 0; r < 4; r++) o[nj][r] = 0.f;

    float m0s = -INFINITY, m1s = -INFINITY, l0s = 0.f, l1s = 0.f;

    __syncthreads();   // all Q-frag reads done before Ps reused in loop

    for (int s0 = 0; s0 < SS; s0 += 64) {
        const int sc = min(64, SS - s0);

        // ---- load K,V chunk [64][64] -> tf32 smem (zero-fill past S) ----
#pragma unroll
        for (int i = 0; i < 8; i++) {
            int idx = tid + i * 128;
            int r = idx >> 4, c = (idx & 15) << 2;
            float4 kv = make_float4(0,0,0,0), vv = kv;
            if (s0 + r < SS) {
                size_t base = (size_t)(b * SS + s0 + r) * DD + h * DH + c;
                kv = *(const float4*)(k + base);
                vv = *(const float4*)(v + base);
            }
            *(float4*)(Ks + r * KSTR + c) = cvt4(kv);
            *(float4*)(Vs + r * VSTR + c) = cvt4(vv);
        }
        __syncthreads();

        // ---- QK^T: 16 rows x 64 s-cols per warp ----
        float qa[8][4];
#pragma unroll
        for (int nj = 0; nj < 8; nj++)
#pragma unroll
            for (int r = 0; r < 4; r++) qa[nj][r] = 0.f;

#pragma unroll
        for (int kk = 0; kk < 8; kk++) {
            uint32_t bfr[8][2];
#pragma unroll
            for (int nj = 0; nj < 8; nj++) {
                int scol = nj * 8 + g;
                bfr[nj][0] = __float_as_uint(Ks[scol * KSTR + kk * 8 + tg]);
                bfr[nj][1] = __float_as_uint(Ks[scol * KSTR + kk * 8 + tg + 4]);
            }
#pragma unroll
            for (int nj = 0; nj < 8; nj++)
                mma8(qa[nj], qf[kk], bfr[nj]);
        }

        // ---- write raw logits; mask out-of-range ----
        {
            size_t rowbase = ((size_t)bh * TT + grow0) * SS + s0;
#pragma unroll
            for (int nj = 0; nj < 8; nj++) {
                int col = nj * 8 + tg * 2;
                if (col < sc) {
                    *(float2*)(qk_out + rowbase + col)          = make_float2(qa[nj][0], qa[nj][1]);
                    *(float2*)(qk_out + rowbase + 8 * SS + col) = make_float2(qa[nj][2], qa[nj][3]);
                } else {
                    qa[nj][0] = qa[nj][1] = -1e30f;
                    qa[nj][2] = qa[nj][3] = -1e30f;
                }
            }
        }

        // ---- warp-local online softmax (2 rows per thread) ----
        float mx0 = -INFINITY, mx1 = -INFINITY;
#pragma unroll
        for (int nj = 0; nj < 8; nj++) {
            mx0 = fmaxf(mx0, fmaxf(qa[nj][0], qa[nj][1]));
            mx1 = fmaxf(mx1, fmaxf(qa[nj][2], qa[nj][3]));
        }
        mx0 = fmaxf(mx0, __shfl_xor_sync(0xffffffffu, mx0, 1));
        mx0 = fmaxf(mx0, __shfl_xor_sync(0xffffffffu, mx0, 2));
        mx1 = fmaxf(mx1, __shfl_xor_sync(0xffffffffu, mx1, 1));
        mx1 = fmaxf(mx1, __shfl_xor_sync(0xffffffffu, mx1, 2));

        float mn0 = fmaxf(m0s, mx0), mn1 = fmaxf(m1s, mx1);
        float c0 = __expf(m0s - mn0), c1 = __expf(m1s - mn1);
        m0s = mn0; m1s = mn1;

        float s0r = 0.f, s1r = 0.f;
#pragma unroll
        for (int nj = 0; nj < 8; nj++) {
            float p0 = __expf(qa[nj][0] - mn0);
            float p1 = __expf(qa[nj][1] - mn0);
            float p2 = __expf(qa[nj][2] - mn1);
            float p3 = __expf(qa[nj][3] - mn1);
            s0r += p0 + p1; s1r += p2 + p3;
            qa[nj][0] = __uint_as_float(f2tf32(p0));
            qa[nj][1] = __uint_as_float(f2tf32(p1));
            qa[nj][2] = __uint_as_float(f2tf32(p2));
            qa[nj][3] = __uint_as_float(f2tf32(p3));
        }
        s0r += __shfl_xor_sync(0xffffffffu, s0r, 1);
        s0r += __shfl_xor_sync(0xffffffffu, s0r, 2);
        s1r += __shfl_xor_sync(0xffffffffu, s1r, 1);
        s1r += __shfl_xor_sync(0xffffffffu, s1r, 2);
        l0s = l0s * c0 + s0r;
        l1s = l1s * c1 + s1r;

        // rescale O
#pragma unroll
        for (int nj = 0; nj < 8; nj++) {
            o[nj][0] *= c0; o[nj][1] *= c0;
            o[nj][2] *= c1; o[nj][3] *= c1;
        }

        // ---- P -> per-warp smem slab (own rows only) ----
#pragma unroll
        for (int nj = 0; nj < 8; nj++) {
            int col = nj * 8 + tg * 2;
            *(float2*)(Ps + (rw + g) * PQSTR + col)     = make_float2(qa[nj][0], qa[nj][1]);
            *(float2*)(Ps + (rw + g + 8) * PQSTR + col) = make_float2(qa[nj][2], qa[nj][3]);
        }
        __syncwarp();

        // ---- PV: O += P @ V ----
#pragma unroll
        for (int kk = 0; kk < 8; kk++) {
            uint32_t af[4], bfr[8][2];
            af[0] = __float_as_uint(Ps[(rw + g) * PQSTR + kk * 8 + tg]);
            af[1] = __float_as_uint(Ps[(rw + g + 8) * PQSTR + kk * 8 + tg]);
            af[2] = __float_as_uint(Ps[(rw + g) * PQSTR + kk * 8 + tg + 4]);
            af[3] = __float_as_uint(Ps[(rw + g + 8) * PQSTR + kk * 8 + tg + 4]);
#pragma unroll
            for (int nj = 0; nj < 8; nj++) {
                int dcol = nj * 8 + g;
                bfr[nj][0] = __float_as_uint(Vs[(kk * 8 + tg) * VSTR + dcol]);
                bfr[nj][1] = __float_as_uint(Vs[(kk * 8 + tg + 4) * VSTR + dcol]);
            }
#pragma unroll
            for (int nj = 0; nj < 8; nj++)
                mma8(o[nj], af, bfr[nj]);
        }
        __syncthreads();   // protect Ks/Vs before next chunk load
    }

    // ---- normalize, write wv ----
    float inv0 = 1.f / l0s, inv1 = 1.f / l1s;
    size_t obase = (size_t)(b * TT + grow0) * DD + h * DH;
#pragma unroll
    for (int nj = 0; nj < 8; nj++) {
        int col = nj * 8 + tg * 2;
        *(float2*)(wv_out + obase + col)          = make_float2(o[nj][0] * inv0, o[nj][1] * inv0);
        *(float2*)(wv_out + obase + 8 * DD + col) = make_float2(o[nj][2] * inv1, o[nj][3] * inv1);
    }
}

// ---------------------------------------------------------------------------
extern "C" void kernel_launch(void* const* d_in, const int* in_sizes, int n_in,
                              void* d_out, int out_size)
{
    const float* x  = (const float*)d_in[0];
    const float* xa = (const float*)d_in[1];
    const float* Wq = (const float*)d_in[2];
    const float* bq = (const float*)d_in[3];
    const float* Wk = (const float*)d_in[4];
    const float* Wv = (const float*)d_in[5];
    const float* bv = (const float*)d_in[6];
    const float* Wo = (const float*)d_in[7];
    const float* bo = (const float*)d_in[8];

    float* out = (float*)d_out;               // [8,448,1024]
    float* qk  = out + OUT_ELEMS;             // [8,16,448,1500]

    float* q_s  = nullptr; cudaGetSymbolAddress((void**)&q_s,  g_q);
    float* k_s  = nullptr; cudaGetSymbolAddress((void**)&k_s,  g_k);
    float* v_s  = nullptr; cudaGetSymbolAddress((void**)&v_s,  g_v);
    float* wv_s = nullptr; cudaGetSymbolAddress((void**)&wv_s, g_wv);

    const float scale = 0.3535533905932738f;  // 64^-0.25

    dim3 blk(128);
    gemm_tf32<<<dim3(DD/128, (BB*TT + 127)/128), blk>>>(x,  Wq, bq,      q_s, BB*TT, DD, DD, scale);
    gemm_tf32<<<dim3(DD/128, (BB*SS + 127)/128), blk>>>(xa, Wk, nullptr, k_s, BB*SS, DD, DD, scale);
    gemm_tf32<<<dim3(DD/128, (BB*SS + 127)/128), blk>>>(xa, Wv, bv,      v_s, BB*SS, DD, DD, 1.0f);

    static const size_t attn_smem = (64 * KSTR + 64 * VSTR + 64 * PQSTR) * sizeof(float);  // 53248
    cudaFuncSetAttribute(attn_tf32, cudaFuncAttributeMaxDynamicSharedMemorySize, (int)attn_smem);
    attn_tf32<<<dim3(TT/64, BB*HH), dim3(128), attn_smem>>>(q_s, k_s, v_s, qk, wv_s);

    gemm_tf32<<<dim3(DD/128, (BB*TT + 127)/128), blk>>>(wv_s, Wo, bo, out, BB*TT, DD, DD, 1.0f);
}